// round 1
// baseline (speedup 1.0000x reference)
#include <cuda_runtime.h>
#include <math.h>

#define BATCH 32
#define CH    96
#define HH    56
#define WW    56
#define HW    3136
#define CHW   301056
#define TOT   9633792
#define EPSV  1e-5f

// ---------------- scratch (static device allocations; no cudaMalloc) --------
__device__ float g_h1[TOT];    // conv1 output
__device__ float g_d [TOT];    // dwconv output
__device__ float g_xlr[TOT];   // LIF along H
__device__ float g_xtd[TOT];   // LIF along W
__device__ float g_t [TOT];    // gelu(conv2_1)+gelu(conv2_2)
__device__ float g_part[BATCH * 672 * 2];   // per-block (sum, sumsq) partials
__device__ float g_st1[BATCH * 2];          // (mu, rstd) per sample
__device__ float g_st2[BATCH * 2];
__device__ float g_st3[BATCH * 2];

__device__ __forceinline__ float gelu_f(float x) {
    return 0.5f * x * (1.0f + erff(x * 0.7071067811865476f));
}

// ---------------- generic 96x96 conv1x1 (GEMM) -------------------------------
// out[b,o,p] = OUT( sum_c w[o,c]*IN(in[b,c,p]) + bias[o] )  [+ out if ACC]
// INM: 0=identity, 2=groupnorm affine (stats + gw/gb)
// OUTM: 0=identity, 1=gelu
// PART: write per-block (sum,sumsq) of stored values
// ACC: accumulate into existing out
template<int INM, int OUTM, int PART, int ACC>
__global__ void __launch_bounds__(256) gemm96_k(
    const float* __restrict__ in, const float* __restrict__ w,
    const float* __restrict__ bias, float* __restrict__ out,
    const float* __restrict__ stats, const float* __restrict__ gw,
    const float* __restrict__ gb, float* __restrict__ part)
{
    __shared__ float smem[48 * 97 + 48 * 112];   // wsm[48][97], xsm[48][112]
    __shared__ float red[512];
    float* wsm = smem;
    float* xsm = smem + 48 * 97;

    const int b   = blockIdx.y;
    const int p0  = blockIdx.x * 112;
    const int tid = threadIdx.x;
    const int ty  = tid >> 4;     // 0..15 -> output rows ty*6..ty*6+5
    const int tx  = tid & 15;     // 0..15 -> pixels tx*7..tx*7+6

    float mu = 0.f, rs = 0.f;
    if (INM != 0) { mu = stats[b * 2]; rs = stats[b * 2 + 1]; }

    float acc[6][7];
#pragma unroll
    for (int i = 0; i < 6; i++)
#pragma unroll
        for (int j = 0; j < 7; j++) acc[i][j] = 0.f;

    const float* inb = in + (size_t)b * CHW + p0;

    for (int kb = 0; kb < 2; kb++) {
        // W panel: w[o][kb*48+kk] -> wsm[kk][o]   (transposed, padded 97)
        for (int i = tid; i < 48 * 96; i += 256) {
            int o = i / 48, kk = i % 48;
            wsm[kk * 97 + o] = w[o * 96 + kb * 48 + kk];
        }
        // X panel with optional input transform
        for (int i = tid; i < 48 * 112; i += 256) {
            int kk = i / 112, p = i % 112;
            int c = kb * 48 + kk;
            float v = inb[(size_t)c * HW + p];
            if (INM == 2) v = (v - mu) * rs * gw[c] + gb[c];
            xsm[kk * 112 + p] = v;
        }
        __syncthreads();
#pragma unroll 4
        for (int kk = 0; kk < 48; kk++) {
            float wr[6], xr[7];
#pragma unroll
            for (int i = 0; i < 6; i++) wr[i] = wsm[kk * 97 + ty * 6 + i];
#pragma unroll
            for (int j = 0; j < 7; j++) xr[j] = xsm[kk * 112 + tx * 7 + j];
#pragma unroll
            for (int i = 0; i < 6; i++)
#pragma unroll
                for (int j = 0; j < 7; j++)
                    acc[i][j] = fmaf(wr[i], xr[j], acc[i][j]);
        }
        __syncthreads();
    }

    float s1 = 0.f, s2 = 0.f;
#pragma unroll
    for (int i = 0; i < 6; i++) {
        const int o = ty * 6 + i;
        const float bi = bias[o];
        float* ob = out + (size_t)b * CHW + (size_t)o * HW + p0;
#pragma unroll
        for (int j = 0; j < 7; j++) {
            const int p = tx * 7 + j;
            float v = acc[i][j] + bi;
            if (OUTM == 1) v = gelu_f(v);
            if (ACC) v += ob[p];
            ob[p] = v;
            if (PART) { s1 += v; s2 += v * v; }
        }
    }

    if (PART) {
        red[tid] = s1; red[256 + tid] = s2;
        __syncthreads();
        for (int off = 128; off > 0; off >>= 1) {
            if (tid < off) {
                red[tid] += red[tid + off];
                red[256 + tid] += red[256 + tid + off];
            }
            __syncthreads();
        }
        if (tid == 0) {
            float* pp = part + ((size_t)b * 28 + blockIdx.x) * 2;
            pp[0] = red[0]; pp[1] = red[256];
        }
    }
}

// ---------------- finalize GN stats: mu, rstd per sample ---------------------
__global__ void __launch_bounds__(256) reduce_k(
    const float* __restrict__ part, int npart, float* __restrict__ stats)
{
    __shared__ float red[512];
    const int b = blockIdx.x, tid = threadIdx.x;
    float s1 = 0.f, s2 = 0.f;
    for (int i = tid; i < npart; i += 256) {
        s1 += part[((size_t)b * npart + i) * 2];
        s2 += part[((size_t)b * npart + i) * 2 + 1];
    }
    red[tid] = s1; red[256 + tid] = s2;
    __syncthreads();
    for (int off = 128; off > 0; off >>= 1) {
        if (tid < off) {
            red[tid] += red[tid + off];
            red[256 + tid] += red[256 + tid + off];
        }
        __syncthreads();
    }
    if (tid == 0) {
        float mu  = red[0]   / (float)CHW;
        float var = red[256] / (float)CHW - mu * mu;
        stats[b * 2]     = mu;
        stats[b * 2 + 1] = rsqrtf(var + EPSV);
    }
}

// ---------------- depthwise 3x3, fused GN1+GELU on load ----------------------
__global__ void __launch_bounds__(256) dw_k(
    const float* __restrict__ in, const float* __restrict__ stats,
    const float* __restrict__ gw, const float* __restrict__ gb,
    const float* __restrict__ dww, const float* __restrict__ dwb,
    float* __restrict__ out, float* __restrict__ part)
{
    __shared__ float tile[10][58];
    __shared__ float red[512];
    const int rt = blockIdx.x;      // 0..6 (8-row tiles)
    const int c  = blockIdx.y;
    const int b  = blockIdx.z;
    const int tid = threadIdx.x;

    const float mu = stats[b * 2], rs = stats[b * 2 + 1];
    const float a  = rs * gw[c];
    const float bb = gb[c] - mu * a;      // gn(v) = v*a + bb
    const float* inb = in + (size_t)(b * CH + c) * HW;
    const int r0 = rt * 8;

    for (int i = tid; i < 580; i += 256) {
        int rr = i / 58, cc = i % 58;
        int gr = r0 - 1 + rr, gc = cc - 1;
        float v = 0.f;
        if (gr >= 0 && gr < HH && gc >= 0 && gc < WW)
            v = gelu_f(inb[gr * WW + gc] * a + bb);
        tile[rr][cc] = v;
    }
    float wd[9];
#pragma unroll
    for (int i = 0; i < 9; i++) wd[i] = dww[c * 9 + i];
    const float bd = dwb[c];
    __syncthreads();

    float s1 = 0.f, s2 = 0.f;
    for (int p = tid; p < 448; p += 256) {
        int lr = p / WW, lc = p % WW;
        float accv = bd;
#pragma unroll
        for (int i = 0; i < 3; i++)
#pragma unroll
            for (int j = 0; j < 3; j++)
                accv = fmaf(wd[i * 3 + j], tile[lr + i][lc + j], accv);
        out[(size_t)(b * CH + c) * HW + (r0 + lr) * WW + lc] = accv;
        s1 += accv; s2 += accv * accv;
    }
    red[tid] = s1; red[256 + tid] = s2;
    __syncthreads();
    for (int off = 128; off > 0; off >>= 1) {
        if (tid < off) {
            red[tid] += red[tid + off];
            red[256 + tid] += red[256 + tid + off];
        }
        __syncthreads();
    }
    if (tid == 0) {
        float* pp = part + ((size_t)b * 672 + c * 7 + rt) * 2;
        pp[0] = red[0]; pp[1] = red[256];
    }
}

// ---------------- LIF scan along H (chunk=4 rows), fused GN2+GELU ------------
__global__ void __launch_bounds__(256) lifH_k(
    const float* __restrict__ in, const float* __restrict__ stats,
    const float* __restrict__ gw, const float* __restrict__ gb,
    const float* __restrict__ tau_p, const float* __restrict__ vth_p,
    float* __restrict__ out)
{
    const int idx = blockIdx.x * 256 + threadIdx.x;
    if (idx >= BATCH * CH * 14 * WW) return;
    const int w  = idx % WW;
    const int hg = (idx / WW) % 14;
    const int c  = (idx / (WW * 14)) % CH;
    const int b  = idx / (WW * 14 * CH);

    const float mu = stats[b * 2], rs = stats[b * 2 + 1];
    const float a  = rs * gw[c];
    const float bb = gb[c] - mu * a;
    const float tau = tau_p[0], vth = vth_p[0];

    const size_t base = (size_t)(b * CH + c) * HW + (size_t)(hg * 4) * WW + w;
    float u = 0.f, s = 0.f;
#pragma unroll
    for (int i = 0; i < 4; i++) {
        float x = gelu_f(in[base + (size_t)i * WW] * a + bb);
        u = x + tau * u * (1.f - s);
        s = (u > vth) ? 1.f : 0.f;
        out[base + (size_t)i * WW] = u * s;
    }
}

// ---------------- LIF scan along W (chunk=4 cols, float4), fused GN2+GELU ----
__global__ void __launch_bounds__(256) lifW_k(
    const float* __restrict__ in, const float* __restrict__ stats,
    const float* __restrict__ gw, const float* __restrict__ gb,
    const float* __restrict__ tau_p, const float* __restrict__ vth_p,
    float* __restrict__ out)
{
    const int idx = blockIdx.x * 256 + threadIdx.x;
    if (idx >= BATCH * CH * HH * 14) return;
    const int wg = idx % 14;
    const int h  = (idx / 14) % HH;
    const int c  = (idx / (14 * HH)) % CH;
    const int b  = idx / (14 * HH * CH);

    const float mu = stats[b * 2], rs = stats[b * 2 + 1];
    const float a  = rs * gw[c];
    const float bb = gb[c] - mu * a;
    const float tau = tau_p[0], vth = vth_p[0];

    const size_t base = (size_t)(b * CH + c) * HW + (size_t)h * WW + wg * 4;
    float4 x4 = *(const float4*)(in + base);
    float xs[4] = {x4.x, x4.y, x4.z, x4.w};
    float ys[4];
    float u = 0.f, s = 0.f;
#pragma unroll
    for (int i = 0; i < 4; i++) {
        float x = gelu_f(xs[i] * a + bb);
        u = x + tau * u * (1.f - s);
        s = (u > vth) ? 1.f : 0.f;
        ys[i] = u * s;
    }
    *(float4*)(out + base) = make_float4(ys[0], ys[1], ys[2], ys[3]);
}

// ---------------- host: 10-launch graph-capturable pipeline ------------------
extern "C" void kernel_launch(void* const* d_in, const int* in_sizes, int n_in,
                              void* d_out, int out_size)
{
    const float* x    = (const float*)d_in[0];
    const float* w1   = (const float*)d_in[1];
    const float* b1   = (const float*)d_in[2];
    const float* n1w  = (const float*)d_in[3];
    const float* n1b  = (const float*)d_in[4];
    const float* dww  = (const float*)d_in[5];
    const float* dwb  = (const float*)d_in[6];
    const float* n2w  = (const float*)d_in[7];
    const float* n2b  = (const float*)d_in[8];
    const float* tau1 = (const float*)d_in[9];
    const float* vth1 = (const float*)d_in[10];
    const float* tau2 = (const float*)d_in[11];
    const float* vth2 = (const float*)d_in[12];
    const float* w21  = (const float*)d_in[13];
    const float* b21  = (const float*)d_in[14];
    const float* w22  = (const float*)d_in[15];
    const float* b22  = (const float*)d_in[16];
    const float* n3w  = (const float*)d_in[17];
    const float* n3b  = (const float*)d_in[18];
    const float* w3   = (const float*)d_in[19];
    const float* b3   = (const float*)d_in[20];
    float* out = (float*)d_out;

    float *h1, *dd, *xlr, *xtd, *tt, *part, *st1, *st2, *st3;
    cudaGetSymbolAddress((void**)&h1,  g_h1);
    cudaGetSymbolAddress((void**)&dd,  g_d);
    cudaGetSymbolAddress((void**)&xlr, g_xlr);
    cudaGetSymbolAddress((void**)&xtd, g_xtd);
    cudaGetSymbolAddress((void**)&tt,  g_t);
    cudaGetSymbolAddress((void**)&part, g_part);
    cudaGetSymbolAddress((void**)&st1, g_st1);
    cudaGetSymbolAddress((void**)&st2, g_st2);
    cudaGetSymbolAddress((void**)&st3, g_st3);

    dim3 gg(28, BATCH);

    // conv1 -> h1, GN1 partials
    gemm96_k<0, 0, 1, 0><<<gg, 256>>>(x, w1, b1, h1, nullptr, nullptr, nullptr, part);
    reduce_k<<<BATCH, 256>>>(part, 28, st1);

    // gelu(gn1(h1)) -> dwconv3x3 -> dd, GN2 partials
    dw_k<<<dim3(7, CH, BATCH), 256>>>(h1, st1, n1w, n1b, dww, dwb, dd, part);
    reduce_k<<<BATCH, 256>>>(part, 672, st2);

    // h2 = gelu(gn2(dd)) computed on the fly; LIF scans
    const int nlif = BATCH * CH * 14 * WW;   // == BATCH*CH*HH*14
    lifH_k<<<(nlif + 255) / 256, 256>>>(dd, st2, n2w, n2b, tau1, vth1, xlr);
    lifW_k<<<(nlif + 255) / 256, 256>>>(dd, st2, n2w, n2b, tau2, vth2, xtd);

    // t = gelu(conv2_1 @ xlr); t += gelu(conv2_2 @ xtd), GN3 partials
    gemm96_k<0, 1, 0, 0><<<gg, 256>>>(xlr, w21, b21, tt, nullptr, nullptr, nullptr, nullptr);
    gemm96_k<0, 1, 1, 1><<<gg, 256>>>(xtd, w22, b22, tt, nullptr, nullptr, nullptr, part);
    reduce_k<<<BATCH, 256>>>(part, 28, st3);

    // out = conv3 @ gn3(t)
    gemm96_k<2, 0, 0, 0><<<gg, 256>>>(tt, w3, b3, out, st3, n3w, n3b, nullptr);
}

// round 2
// speedup vs baseline: 1.2499x; 1.2499x over previous
#include <cuda_runtime.h>
#include <math.h>

#define BATCH 32
#define CH    96
#define HH    56
#define WW    56
#define HW    3136
#define CHW   301056
#define TOT   9633792
#define EPSV  1e-5f

// ---------------- scratch (static device allocations) ------------------------
__device__ float g_h1[TOT];    // conv1 output
__device__ float g_d [TOT];    // dwconv output
__device__ float g_xlr[TOT];   // LIF along H
__device__ float g_xtd[TOT];   // LIF along W
__device__ float g_t [TOT];    // gelu(conv2_1)+gelu(conv2_2)
__device__ float g_part[BATCH * 256 * 2];
__device__ float g_st1[BATCH * 2];
__device__ float g_st2[BATCH * 2];
__device__ float g_st3[BATCH * 2];

__device__ __forceinline__ float gelu_f(float x) {
    return 0.5f * x * (1.0f + erff(x * 0.7071067811865476f));
}

// ---------------- 96x96 conv1x1 GEMM, CTA tile 96 x 128 px -------------------
// out[b,o,p] = OUT( sum_c w[o,c] * IN(in[b,c,p]) + bias[o] )
// DUAL: out = gelu(w1@in1+b1) + gelu(w2@in2+b2)
// INM: 0 identity, 2 groupnorm-affine on input
// OUTM: 1 gelu on output (non-dual path)
// PART: emit per-block (sum,sumsq)
template<int INM, int OUTM, int PART, int DUAL>
__global__ void __launch_bounds__(256, DUAL ? 1 : 2) gemm96_k(
    const float* __restrict__ in,  const float* __restrict__ w,
    const float* __restrict__ bias,
    const float* __restrict__ in2, const float* __restrict__ w2,
    const float* __restrict__ bias2,
    float* __restrict__ out,
    const float* __restrict__ stats, const float* __restrict__ gw,
    const float* __restrict__ gb, float* __restrict__ part)
{
    __shared__ float wsm[96 * 33];     // [o][kk], pad 33
    __shared__ float xsm[32 * 128];    // [kk][px]
    __shared__ float red[512];

    const int b   = blockIdx.y;
    const int p0  = blockIdx.x * 128;
    const int tid = threadIdx.x;
    const int ty  = tid >> 4;          // 0..15 : rows ty*6..+5
    const int tx  = tid & 15;          // 0..15 : px tx*4 and 64+tx*4

    float mu = 0.f, rs = 0.f;
    if (INM == 2) { mu = stats[b * 2]; rs = stats[b * 2 + 1]; }

    float acc[6][8];
    float r1[6][8];                    // DUAL first-gemm result
    const float4* xsm4 = (const float4*)xsm;
    const int woff = ty * 6 * 33;

    for (int pass = 0; pass < (DUAL ? 2 : 1); pass++) {
        const float* inp = (DUAL && pass == 1) ? in2 : in;
        const float* wp  = (DUAL && pass == 1) ? w2  : w;
        const float* inb = inp + (size_t)b * CHW + p0;

#pragma unroll
        for (int i = 0; i < 6; i++)
#pragma unroll
            for (int j = 0; j < 8; j++) acc[i][j] = 0.f;

        for (int kb = 0; kb < 3; kb++) {
            // W panel: 96 x 32
            for (int j = tid; j < 3072; j += 256) {
                int o = j >> 5, kk = j & 31;
                wsm[o * 33 + kk] = wp[o * 96 + kb * 32 + kk];
            }
            // X panel: 32 x 128 (float4, guarded)
            for (int f = tid; f < 1024; f += 256) {
                int kk = f >> 5, px = (f & 31) * 4;
                int c = kb * 32 + kk;
                float4 v = make_float4(0.f, 0.f, 0.f, 0.f);
                if (p0 + px < HW) {
                    v = *(const float4*)(inb + (size_t)c * HW + px);
                    if (INM == 2) {
                        float a = rs * gw[c], bb = gb[c] - mu * a;
                        v.x = v.x * a + bb; v.y = v.y * a + bb;
                        v.z = v.z * a + bb; v.w = v.w * a + bb;
                    }
                }
                *(float4*)(xsm + kk * 128 + px) = v;
            }
            __syncthreads();
#pragma unroll 4
            for (int kk = 0; kk < 32; kk++) {
                float4 x0 = xsm4[kk * 32 + tx];        // px = tx*4
                float4 x1 = xsm4[kk * 32 + 16 + tx];   // px = 64+tx*4
                float wr[6];
#pragma unroll
                for (int i = 0; i < 6; i++) wr[i] = wsm[woff + i * 33 + kk];
#pragma unroll
                for (int i = 0; i < 6; i++) {
                    acc[i][0] = fmaf(wr[i], x0.x, acc[i][0]);
                    acc[i][1] = fmaf(wr[i], x0.y, acc[i][1]);
                    acc[i][2] = fmaf(wr[i], x0.z, acc[i][2]);
                    acc[i][3] = fmaf(wr[i], x0.w, acc[i][3]);
                    acc[i][4] = fmaf(wr[i], x1.x, acc[i][4]);
                    acc[i][5] = fmaf(wr[i], x1.y, acc[i][5]);
                    acc[i][6] = fmaf(wr[i], x1.z, acc[i][6]);
                    acc[i][7] = fmaf(wr[i], x1.w, acc[i][7]);
                }
            }
            __syncthreads();
        }

        if (DUAL && pass == 0) {
#pragma unroll
            for (int i = 0; i < 6; i++) {
                float bi = bias[ty * 6 + i];
#pragma unroll
                for (int j = 0; j < 8; j++) r1[i][j] = gelu_f(acc[i][j] + bi);
            }
        }
    }

    // epilogue
    const bool g2 = (p0 + 64 + tx * 4) < HW;   // first half always valid
    float s1 = 0.f, s2 = 0.f;
#pragma unroll
    for (int i = 0; i < 6; i++) {
        const int o = ty * 6 + i;
        const float bi = DUAL ? bias2[o] : bias[o];
        float* ob = out + (size_t)b * CHW + (size_t)o * HW + p0;
        float v[8];
#pragma unroll
        for (int j = 0; j < 8; j++) {
            float t = acc[i][j] + bi;
            if (OUTM == 1 || DUAL) t = gelu_f(t);
            if (DUAL) t += r1[i][j];
            v[j] = t;
        }
        *(float4*)(ob + tx * 4) = make_float4(v[0], v[1], v[2], v[3]);
        if (g2) *(float4*)(ob + 64 + tx * 4) = make_float4(v[4], v[5], v[6], v[7]);
        if (PART) {
#pragma unroll
            for (int j = 0; j < 4; j++) { s1 += v[j]; s2 += v[j] * v[j]; }
            if (g2)
#pragma unroll
                for (int j = 4; j < 8; j++) { s1 += v[j]; s2 += v[j] * v[j]; }
        }
    }

    if (PART) {
        red[tid] = s1; red[256 + tid] = s2;
        __syncthreads();
        for (int off = 128; off > 0; off >>= 1) {
            if (tid < off) {
                red[tid] += red[tid + off];
                red[256 + tid] += red[256 + tid + off];
            }
            __syncthreads();
        }
        if (tid == 0) {
            float* pp = part + ((size_t)b * gridDim.x + blockIdx.x) * 2;
            pp[0] = red[0]; pp[1] = red[256];
        }
    }
}

// ---------------- finalize GN stats ------------------------------------------
__global__ void __launch_bounds__(256) reduce_k(
    const float* __restrict__ part, int npart, float* __restrict__ stats)
{
    __shared__ float red[512];
    const int b = blockIdx.x, tid = threadIdx.x;
    float s1 = 0.f, s2 = 0.f;
    for (int i = tid; i < npart; i += 256) {
        s1 += part[((size_t)b * npart + i) * 2];
        s2 += part[((size_t)b * npart + i) * 2 + 1];
    }
    red[tid] = s1; red[256 + tid] = s2;
    __syncthreads();
    for (int off = 128; off > 0; off >>= 1) {
        if (tid < off) {
            red[tid] += red[tid + off];
            red[256 + tid] += red[256 + tid + off];
        }
        __syncthreads();
    }
    if (tid == 0) {
        float mu  = red[0]   / (float)CHW;
        float var = red[256] / (float)CHW - mu * mu;
        stats[b * 2]     = mu;
        stats[b * 2 + 1] = rsqrtf(var + EPSV);
    }
}

// ---------------- depthwise 3x3, fused GN1+GELU, 28-row tiles ----------------
__global__ void __launch_bounds__(256) dw_k(
    const float* __restrict__ in, const float* __restrict__ stats,
    const float* __restrict__ gw, const float* __restrict__ gb,
    const float* __restrict__ dww, const float* __restrict__ dwb,
    float* __restrict__ out, float* __restrict__ part)
{
    __shared__ float tile[30][58];
    __shared__ float red[512];
    const int rt = blockIdx.x;      // 0..1 (28-row tiles)
    const int c  = blockIdx.y;
    const int b  = blockIdx.z;
    const int tid = threadIdx.x;

    const float mu = stats[b * 2], rs = stats[b * 2 + 1];
    const float a  = rs * gw[c];
    const float bb = gb[c] - mu * a;
    const float* inb = in + (size_t)(b * CH + c) * HW;
    const int r0 = rt * 28;

    for (int i = tid; i < 30 * 58; i += 256) {
        int rr = i / 58, cc = i % 58;
        int gr = r0 - 1 + rr, gc = cc - 1;
        float v = 0.f;
        if (gr >= 0 && gr < HH && gc >= 0 && gc < WW)
            v = gelu_f(inb[gr * WW + gc] * a + bb);
        tile[rr][cc] = v;
    }
    float wd[9];
#pragma unroll
    for (int i = 0; i < 9; i++) wd[i] = dww[c * 9 + i];
    const float bd = dwb[c];
    __syncthreads();

    float s1 = 0.f, s2 = 0.f;
    for (int p = tid; p < 28 * 56; p += 256) {
        int lr = p / 56, lc = p % 56;
        float accv = bd;
#pragma unroll
        for (int i = 0; i < 3; i++)
#pragma unroll
            for (int j = 0; j < 3; j++)
                accv = fmaf(wd[i * 3 + j], tile[lr + i][lc + j], accv);
        out[(size_t)(b * CH + c) * HW + (r0 + lr) * WW + lc] = accv;
        s1 += accv; s2 += accv * accv;
    }
    red[tid] = s1; red[256 + tid] = s2;
    __syncthreads();
    for (int off = 128; off > 0; off >>= 1) {
        if (tid < off) {
            red[tid] += red[tid + off];
            red[256 + tid] += red[256 + tid + off];
        }
        __syncthreads();
    }
    if (tid == 0) {
        float* pp = part + ((size_t)b * 192 + c * 2 + rt) * 2;
        pp[0] = red[0]; pp[1] = red[256];
    }
}

// ---------------- fused LIF: both H-scan and W-scan on a 4x4 tile ------------
__global__ void __launch_bounds__(256) lif_k(
    const float* __restrict__ in, const float* __restrict__ stats,
    const float* __restrict__ gw, const float* __restrict__ gb,
    const float* __restrict__ tau1_p, const float* __restrict__ vth1_p,
    const float* __restrict__ tau2_p, const float* __restrict__ vth2_p,
    float* __restrict__ xlr, float* __restrict__ xtd)
{
    const int idx = blockIdx.x * 256 + threadIdx.x;
    if (idx >= BATCH * CH * 14 * 14) return;
    const int wg = idx % 14;
    const int hg = (idx / 14) % 14;
    const int c  = (idx / 196) % CH;
    const int b  = idx / (196 * CH);

    const float mu = stats[b * 2], rs = stats[b * 2 + 1];
    const float a  = rs * gw[c];
    const float bb = gb[c] - mu * a;
    const float tau1 = tau1_p[0], vth1 = vth1_p[0];
    const float tau2 = tau2_p[0], vth2 = vth2_p[0];

    const size_t base = (size_t)(b * CH + c) * HW + (size_t)(hg * 4) * WW + wg * 4;

    float g[4][4];
#pragma unroll
    for (int i = 0; i < 4; i++) {
        float4 v = *(const float4*)(in + base + (size_t)i * WW);
        g[i][0] = gelu_f(v.x * a + bb);
        g[i][1] = gelu_f(v.y * a + bb);
        g[i][2] = gelu_f(v.z * a + bb);
        g[i][3] = gelu_f(v.w * a + bb);
    }
    // W-scan (axis=3): per row
#pragma unroll
    for (int i = 0; i < 4; i++) {
        float u = 0.f, s = 0.f, y[4];
#pragma unroll
        for (int j = 0; j < 4; j++) {
            u = g[i][j] + tau2 * u * (1.f - s);
            s = (u > vth2) ? 1.f : 0.f;
            y[j] = u * s;
        }
        *(float4*)(xtd + base + (size_t)i * WW) = make_float4(y[0], y[1], y[2], y[3]);
    }
    // H-scan (axis=2): per column
    float yl[4][4];
#pragma unroll
    for (int j = 0; j < 4; j++) {
        float u = 0.f, s = 0.f;
#pragma unroll
        for (int i = 0; i < 4; i++) {
            u = g[i][j] + tau1 * u * (1.f - s);
            s = (u > vth1) ? 1.f : 0.f;
            yl[i][j] = u * s;
        }
    }
#pragma unroll
    for (int i = 0; i < 4; i++)
        *(float4*)(xlr + base + (size_t)i * WW) =
            make_float4(yl[i][0], yl[i][1], yl[i][2], yl[i][3]);
}

// ---------------- host pipeline (8 launches, graph-capturable) ---------------
extern "C" void kernel_launch(void* const* d_in, const int* in_sizes, int n_in,
                              void* d_out, int out_size)
{
    const float* x    = (const float*)d_in[0];
    const float* w1   = (const float*)d_in[1];
    const float* b1   = (const float*)d_in[2];
    const float* n1w  = (const float*)d_in[3];
    const float* n1b  = (const float*)d_in[4];
    const float* dww  = (const float*)d_in[5];
    const float* dwb  = (const float*)d_in[6];
    const float* n2w  = (const float*)d_in[7];
    const float* n2b  = (const float*)d_in[8];
    const float* tau1 = (const float*)d_in[9];
    const float* vth1 = (const float*)d_in[10];
    const float* tau2 = (const float*)d_in[11];
    const float* vth2 = (const float*)d_in[12];
    const float* w21  = (const float*)d_in[13];
    const float* b21  = (const float*)d_in[14];
    const float* w22  = (const float*)d_in[15];
    const float* b22  = (const float*)d_in[16];
    const float* n3w  = (const float*)d_in[17];
    const float* n3b  = (const float*)d_in[18];
    const float* w3   = (const float*)d_in[19];
    const float* b3   = (const float*)d_in[20];
    float* out = (float*)d_out;

    float *h1, *dd, *xlr, *xtd, *tt, *part, *st1, *st2, *st3;
    cudaGetSymbolAddress((void**)&h1,  g_h1);
    cudaGetSymbolAddress((void**)&dd,  g_d);
    cudaGetSymbolAddress((void**)&xlr, g_xlr);
    cudaGetSymbolAddress((void**)&xtd, g_xtd);
    cudaGetSymbolAddress((void**)&tt,  g_t);
    cudaGetSymbolAddress((void**)&part, g_part);
    cudaGetSymbolAddress((void**)&st1, g_st1);
    cudaGetSymbolAddress((void**)&st2, g_st2);
    cudaGetSymbolAddress((void**)&st3, g_st3);

    dim3 gg(25, BATCH);   // ceil(3136/128) = 25

    // conv1 -> h1, GN1 partials
    gemm96_k<0, 0, 1, 0><<<gg, 256>>>(x, w1, b1, nullptr, nullptr, nullptr,
                                      h1, nullptr, nullptr, nullptr, part);
    reduce_k<<<BATCH, 256>>>(part, 25, st1);

    // gelu(gn1(h1)) -> dwconv -> dd, GN2 partials
    dw_k<<<dim3(2, CH, BATCH), 256>>>(h1, st1, n1w, n1b, dww, dwb, dd, part);
    reduce_k<<<BATCH, 256>>>(part, 192, st2);

    // fused LIF (gelu(gn2(dd)) on the fly) -> xlr, xtd
    const int nlif = BATCH * CH * 14 * 14;
    lif_k<<<(nlif + 255) / 256, 256>>>(dd, st2, n2w, n2b,
                                       tau1, vth1, tau2, vth2, xlr, xtd);

    // tt = gelu(w21@xlr+b21) + gelu(w22@xtd+b22), GN3 partials
    gemm96_k<0, 0, 1, 1><<<gg, 256>>>(xlr, w21, b21, xtd, w22, b22,
                                      tt, nullptr, nullptr, nullptr, part);
    reduce_k<<<BATCH, 256>>>(part, 25, st3);

    // out = conv3 @ gn3(tt)
    gemm96_k<2, 0, 0, 0><<<gg, 256>>>(tt, w3, b3, nullptr, nullptr, nullptr,
                                      out, st3, n3w, n3b, nullptr);
}

// round 5
// speedup vs baseline: 1.8416x; 1.4734x over previous
#include <cuda_runtime.h>
#include <cuda_bf16.h>
#include <math.h>
#include <stdint.h>

#define BATCH 32
#define CH    96
#define HH    56
#define WW    56
#define HW    3136
#define CHW   301056
#define TOT   9633792
#define EPSV  1e-5f

// ---------------- scratch ----------------------------------------------------
__device__ float g_h1[TOT];
__device__ float g_d [TOT];
__device__ float g_xlr[TOT];
__device__ float g_xtd[TOT];
__device__ float g_t [TOT];
__device__ float g_part[BATCH * 256 * 2];
__device__ float g_st1[BATCH * 2];
__device__ float g_st2[BATCH * 2];
__device__ float g_st3[BATCH * 2];

__device__ __forceinline__ float gelu_f(float x) {
    return 0.5f * x * (1.0f + erff(x * 0.7071067811865476f));
}

__device__ __forceinline__ uint32_t pack2(float lo, float hi) {
    __nv_bfloat162 t = __floats2bfloat162_rn(lo, hi);
    return *(uint32_t*)&t;
}

__device__ __forceinline__ void mma16816(float& d0, float& d1, float& d2, float& d3,
                                         uint32_t a0, uint32_t a1, uint32_t a2, uint32_t a3,
                                         uint32_t b0, uint32_t b1) {
    asm volatile(
        "mma.sync.aligned.m16n8k16.row.col.f32.bf16.bf16.f32 "
        "{%0,%1,%2,%3}, {%4,%5,%6,%7}, {%8,%9}, {%0,%1,%2,%3};"
        : "+f"(d0), "+f"(d1), "+f"(d2), "+f"(d3)
        : "r"(a0), "r"(a1), "r"(a2), "r"(a3), "r"(b0), "r"(b1));
}

// ---------------- tensor-core (mma.sync) 96x96 conv1x1 -----------------------
// D[o, px] = sum_c W[o,c] * X(in[b,c,px]); split-bf16 (3 passes), fp32 accum.
// A = weights 16x16 frags (from global, in regs). B = activations in SMEM
// [px][c] bf16, row stride 104 (conflict-free frag loads).
// INM: 2 = gn-affine input. OUTM: 1 = gelu. PART: GN partials. ACC: +=out.
#define BSTR 104
template<int INM, int OUTM, int PART, int ACC>
__global__ void __launch_bounds__(192, 2) gemm_mma(
    const float* __restrict__ in, const float* __restrict__ w,
    const float* __restrict__ bias, float* __restrict__ out,
    const float* __restrict__ stats, const float* __restrict__ gw,
    const float* __restrict__ gb, float* __restrict__ part)
{
    extern __shared__ char dsm[];
    __nv_bfloat16* bhm = (__nv_bfloat16*)dsm;            // [128][104]
    __nv_bfloat16* blm = bhm + 128 * BSTR;               // [128][104]
    float* red = (float*)(dsm + 128 * BSTR * 2 * 2);

    const int b    = blockIdx.y;
    const int p0   = blockIdx.x * 128;
    const int tid  = threadIdx.x;
    const int warp = tid >> 5, lane = tid & 31;
    const int gid  = lane >> 2, tig = lane & 3;
    const int o0   = warp * 16;

    float mu = 0.f, rs = 0.f;
    if (INM == 2) { mu = stats[2 * b]; rs = stats[2 * b + 1]; }

    // ---- B: activations -> SMEM bf16 hi/lo, [px][c] ------------------------
    const float* inb = in + (size_t)b * CHW + p0;
    for (int i = tid; i < CH * 128; i += 192) {
        const int px = i & 127, c = i >> 7;
        float v = 0.f;
        if (p0 + px < HW) v = inb[(size_t)c * HW + px];
        if (INM == 2) { float a = rs * gw[c]; v = v * a + (gb[c] - mu * a); }
        const __nv_bfloat16 h = __float2bfloat16_rn(v);
        const __nv_bfloat16 l = __float2bfloat16_rn(v - __bfloat162float(h));
        bhm[px * BSTR + c] = h;
        blm[px * BSTR + c] = l;
    }

    // ---- A: weight fragments (hi/lo) straight from global ------------------
    uint32_t aH[6][4], aL[6][4];
    const float* w0 = w + (size_t)(o0 + gid) * CH;
#pragma unroll
    for (int s = 0; s < 6; s++) {
        const int c0 = s * 16 + 2 * tig;
#pragma unroll
        for (int q = 0; q < 4; q++) {
            const int roff = (q & 1) ? 8 * CH : 0;    // a1,a3: row+8
            const int coff = (q & 2) ? 8 : 0;         // a2,a3: col+8
            const float f0 = __ldg(&w0[roff + c0 + coff]);
            const float f1 = __ldg(&w0[roff + c0 + coff + 1]);
            const __nv_bfloat16 h0 = __float2bfloat16_rn(f0);
            const __nv_bfloat16 h1 = __float2bfloat16_rn(f1);
            aH[s][q] = pack2(__bfloat162float(h0), __bfloat162float(h1));
            aL[s][q] = pack2(f0 - __bfloat162float(h0), f1 - __bfloat162float(h1));
        }
    }
    __syncthreads();

    const float bias0 = bias[o0 + gid];
    const float bias1 = bias[o0 + gid + 8];
    float s1 = 0.f, s2 = 0.f;
    float* ob = out + (size_t)b * CHW;

    // ---- 16 n-tiles of 8 px ------------------------------------------------
    for (int nt = 0; nt < 16; nt++) {
        float d0 = 0.f, d1 = 0.f, d2 = 0.f, d3 = 0.f;
        const __nv_bfloat16* bhp = bhm + (nt * 8 + gid) * BSTR + 2 * tig;
        const __nv_bfloat16* blp = blm + (nt * 8 + gid) * BSTR + 2 * tig;
#pragma unroll
        for (int s = 0; s < 6; s++) {
            const uint32_t bh0 = *(const uint32_t*)(bhp + 16 * s);
            const uint32_t bh1 = *(const uint32_t*)(bhp + 16 * s + 8);
            const uint32_t bl0 = *(const uint32_t*)(blp + 16 * s);
            const uint32_t bl1 = *(const uint32_t*)(blp + 16 * s + 8);
            mma16816(d0, d1, d2, d3, aH[s][0], aH[s][1], aH[s][2], aH[s][3], bh0, bh1);
            mma16816(d0, d1, d2, d3, aL[s][0], aL[s][1], aL[s][2], aL[s][3], bh0, bh1);
            mma16816(d0, d1, d2, d3, aH[s][0], aH[s][1], aH[s][2], aH[s][3], bl0, bl1);
        }
        const int px = p0 + nt * 8 + 2 * tig;
        if (px < HW) {
            float v00 = d0 + bias0, v01 = d1 + bias0;
            float v10 = d2 + bias1, v11 = d3 + bias1;
            if (OUTM == 1) {
                v00 = gelu_f(v00); v01 = gelu_f(v01);
                v10 = gelu_f(v10); v11 = gelu_f(v11);
            }
            float* p00 = ob + (size_t)(o0 + gid) * HW + px;
            float* p10 = ob + (size_t)(o0 + gid + 8) * HW + px;
            if (ACC) {
                float2 t0 = *(float2*)p00; v00 += t0.x; v01 += t0.y;
                float2 t1 = *(float2*)p10; v10 += t1.x; v11 += t1.y;
            }
            *(float2*)p00 = make_float2(v00, v01);
            *(float2*)p10 = make_float2(v10, v11);
            if (PART) {
                s1 += v00 + v01 + v10 + v11;
                s2 += v00 * v00 + v01 * v01 + v10 * v10 + v11 * v11;
            }
        }
    }

    if (PART) {
#pragma unroll
        for (int off = 16; off > 0; off >>= 1) {
            s1 += __shfl_xor_sync(0xFFFFFFFFu, s1, off);
            s2 += __shfl_xor_sync(0xFFFFFFFFu, s2, off);
        }
        if (lane == 0) { red[warp] = s1; red[6 + warp] = s2; }
        __syncthreads();
        if (tid == 0) {
            float t1 = 0.f, t2 = 0.f;
#pragma unroll
            for (int i = 0; i < 6; i++) { t1 += red[i]; t2 += red[6 + i]; }
            float* pp = part + ((size_t)b * gridDim.x + blockIdx.x) * 2;
            pp[0] = t1; pp[1] = t2;
        }
    }
}

// ---------------- finalize GN stats ------------------------------------------
__global__ void __launch_bounds__(256) reduce_k(
    const float* __restrict__ part, int npart, float* __restrict__ stats)
{
    __shared__ float red[512];
    const int b = blockIdx.x, tid = threadIdx.x;
    float s1 = 0.f, s2 = 0.f;
    for (int i = tid; i < npart; i += 256) {
        s1 += part[((size_t)b * npart + i) * 2];
        s2 += part[((size_t)b * npart + i) * 2 + 1];
    }
    red[tid] = s1; red[256 + tid] = s2;
    __syncthreads();
    for (int off = 128; off > 0; off >>= 1) {
        if (tid < off) {
            red[tid] += red[tid + off];
            red[256 + tid] += red[256 + tid + off];
        }
        __syncthreads();
    }
    if (tid == 0) {
        float mu  = red[0]   / (float)CHW;
        float var = red[256] / (float)CHW - mu * mu;
        stats[b * 2]     = mu;
        stats[b * 2 + 1] = rsqrtf(var + EPSV);
    }
}

// ---------------- depthwise 3x3, fused GN1+GELU ------------------------------
__global__ void __launch_bounds__(256) dw_k(
    const float* __restrict__ in, const float* __restrict__ stats,
    const float* __restrict__ gw, const float* __restrict__ gb,
    const float* __restrict__ dww, const float* __restrict__ dwb,
    float* __restrict__ out, float* __restrict__ part)
{
    __shared__ float tile[30][58];
    __shared__ float red[512];
    const int rt = blockIdx.x;
    const int c  = blockIdx.y;
    const int b  = blockIdx.z;
    const int tid = threadIdx.x;

    const float mu = stats[b * 2], rs = stats[b * 2 + 1];
    const float a  = rs * gw[c];
    const float bb = gb[c] - mu * a;
    const float* inb = in + (size_t)(b * CH + c) * HW;
    const int r0 = rt * 28;

    for (int i = tid; i < 30 * 58; i += 256) {
        int rr = i / 58, cc = i % 58;
        int gr = r0 - 1 + rr, gc = cc - 1;
        float v = 0.f;
        if (gr >= 0 && gr < HH && gc >= 0 && gc < WW)
            v = gelu_f(inb[gr * WW + gc] * a + bb);
        tile[rr][cc] = v;
    }
    float wd[9];
#pragma unroll
    for (int i = 0; i < 9; i++) wd[i] = dww[c * 9 + i];
    const float bd = dwb[c];
    __syncthreads();

    float s1 = 0.f, s2 = 0.f;
    for (int p = tid; p < 28 * 56; p += 256) {
        int lr = p / 56, lc = p % 56;
        float accv = bd;
#pragma unroll
        for (int i = 0; i < 3; i++)
#pragma unroll
            for (int j = 0; j < 3; j++)
                accv = fmaf(wd[i * 3 + j], tile[lr + i][lc + j], accv);
        out[(size_t)(b * CH + c) * HW + (r0 + lr) * WW + lc] = accv;
        s1 += accv; s2 += accv * accv;
    }
    red[tid] = s1; red[256 + tid] = s2;
    __syncthreads();
    for (int off = 128; off > 0; off >>= 1) {
        if (tid < off) {
            red[tid] += red[tid + off];
            red[256 + tid] += red[256 + tid + off];
        }
        __syncthreads();
    }
    if (tid == 0) {
        float* pp = part + ((size_t)b * 192 + c * 2 + rt) * 2;
        pp[0] = red[0]; pp[1] = red[256];
    }
}

// ---------------- fused LIF (H and W scans, 4x4 tile) ------------------------
__global__ void __launch_bounds__(256) lif_k(
    const float* __restrict__ in, const float* __restrict__ stats,
    const float* __restrict__ gw, const float* __restrict__ gb,
    const float* __restrict__ tau1_p, const float* __restrict__ vth1_p,
    const float* __restrict__ tau2_p, const float* __restrict__ vth2_p,
    float* __restrict__ xlr, float* __restrict__ xtd)
{
    const int idx = blockIdx.x * 256 + threadIdx.x;
    if (idx >= BATCH * CH * 14 * 14) return;
    const int wg = idx % 14;
    const int hg = (idx / 14) % 14;
    const int c  = (idx / 196) % CH;
    const int b  = idx / (196 * CH);

    const float mu = stats[b * 2], rs = stats[b * 2 + 1];
    const float a  = rs * gw[c];
    const float bb = gb[c] - mu * a;
    const float tau1 = tau1_p[0], vth1 = vth1_p[0];
    const float tau2 = tau2_p[0], vth2 = vth2_p[0];

    const size_t base = (size_t)(b * CH + c) * HW + (size_t)(hg * 4) * WW + wg * 4;

    float g[4][4];
#pragma unroll
    for (int i = 0; i < 4; i++) {
        float4 v = *(const float4*)(in + base + (size_t)i * WW);
        g[i][0] = gelu_f(v.x * a + bb);
        g[i][1] = gelu_f(v.y * a + bb);
        g[i][2] = gelu_f(v.z * a + bb);
        g[i][3] = gelu_f(v.w * a + bb);
    }
#pragma unroll
    for (int i = 0; i < 4; i++) {
        float u = 0.f, s = 0.f, y[4];
#pragma unroll
        for (int j = 0; j < 4; j++) {
            u = g[i][j] + tau2 * u * (1.f - s);
            s = (u > vth2) ? 1.f : 0.f;
            y[j] = u * s;
        }
        *(float4*)(xtd + base + (size_t)i * WW) = make_float4(y[0], y[1], y[2], y[3]);
    }
    float yl[4][4];
#pragma unroll
    for (int j = 0; j < 4; j++) {
        float u = 0.f, s = 0.f;
#pragma unroll
        for (int i = 0; i < 4; i++) {
            u = g[i][j] + tau1 * u * (1.f - s);
            s = (u > vth1) ? 1.f : 0.f;
            yl[i][j] = u * s;
        }
    }
#pragma unroll
    for (int i = 0; i < 4; i++)
        *(float4*)(xlr + base + (size_t)i * WW) =
            make_float4(yl[i][0], yl[i][1], yl[i][2], yl[i][3]);
}

// ---------------- host pipeline ----------------------------------------------
#define GEMM_SMEM (128 * BSTR * 2 * 2 + 64)

extern "C" void kernel_launch(void* const* d_in, const int* in_sizes, int n_in,
                              void* d_out, int out_size)
{
    const float* x    = (const float*)d_in[0];
    const float* w1   = (const float*)d_in[1];
    const float* b1   = (const float*)d_in[2];
    const float* n1w  = (const float*)d_in[3];
    const float* n1b  = (const float*)d_in[4];
    const float* dww  = (const float*)d_in[5];
    const float* dwb  = (const float*)d_in[6];
    const float* n2w  = (const float*)d_in[7];
    const float* n2b  = (const float*)d_in[8];
    const float* tau1 = (const float*)d_in[9];
    const float* vth1 = (const float*)d_in[10];
    const float* tau2 = (const float*)d_in[11];
    const float* vth2 = (const float*)d_in[12];
    const float* w21  = (const float*)d_in[13];
    const float* b21  = (const float*)d_in[14];
    const float* w22  = (const float*)d_in[15];
    const float* b22  = (const float*)d_in[16];
    const float* n3w  = (const float*)d_in[17];
    const float* n3b  = (const float*)d_in[18];
    const float* w3   = (const float*)d_in[19];
    const float* b3   = (const float*)d_in[20];
    float* out = (float*)d_out;

    float *h1, *dd, *xlr, *xtd, *tt, *part, *st1, *st2, *st3;
    cudaGetSymbolAddress((void**)&h1,  g_h1);
    cudaGetSymbolAddress((void**)&dd,  g_d);
    cudaGetSymbolAddress((void**)&xlr, g_xlr);
    cudaGetSymbolAddress((void**)&xtd, g_xtd);
    cudaGetSymbolAddress((void**)&tt,  g_t);
    cudaGetSymbolAddress((void**)&part, g_part);
    cudaGetSymbolAddress((void**)&st1, g_st1);
    cudaGetSymbolAddress((void**)&st2, g_st2);
    cudaGetSymbolAddress((void**)&st3, g_st3);

    cudaFuncSetAttribute(gemm_mma<0,0,1,0>, cudaFuncAttributeMaxDynamicSharedMemorySize, GEMM_SMEM);
    cudaFuncSetAttribute(gemm_mma<0,1,0,0>, cudaFuncAttributeMaxDynamicSharedMemorySize, GEMM_SMEM);
    cudaFuncSetAttribute(gemm_mma<0,1,1,1>, cudaFuncAttributeMaxDynamicSharedMemorySize, GEMM_SMEM);
    cudaFuncSetAttribute(gemm_mma<2,0,0,0>, cudaFuncAttributeMaxDynamicSharedMemorySize, GEMM_SMEM);

    dim3 gg(25, BATCH);

    // conv1 -> h1, GN1 partials
    gemm_mma<0,0,1,0><<<gg, 192, GEMM_SMEM>>>(x, w1, b1, h1, nullptr, nullptr, nullptr, part);
    reduce_k<<<BATCH, 256>>>(part, 25, st1);

    // gelu(gn1(h1)) -> dwconv -> dd, GN2 partials
    dw_k<<<dim3(2, CH, BATCH), 256>>>(h1, st1, n1w, n1b, dww, dwb, dd, part);
    reduce_k<<<BATCH, 256>>>(part, 192, st2);

    // fused LIF
    const int nlif = BATCH * CH * 14 * 14;
    lif_k<<<(nlif + 255) / 256, 256>>>(dd, st2, n2w, n2b, tau1, vth1, tau2, vth2, xlr, xtd);

    // tt = gelu(w21@xlr+b21); tt += gelu(w22@xtd+b22), GN3 partials
    gemm_mma<0,1,0,0><<<gg, 192, GEMM_SMEM>>>(xlr, w21, b21, tt, nullptr, nullptr, nullptr, nullptr);
    gemm_mma<0,1,1,1><<<gg, 192, GEMM_SMEM>>>(xtd, w22, b22, tt, nullptr, nullptr, nullptr, part);
    reduce_k<<<BATCH, 256>>>(part, 25, st3);

    // out = conv3 @ gn3(tt)
    gemm_mma<2,0,0,0><<<gg, 192, GEMM_SMEM>>>(tt, w3, b3, out, st3, n3w, n3b, nullptr);
}